// round 13
// baseline (speedup 1.0000x reference)
#include <cuda_runtime.h>
#include <cuda_fp16.h>
#include <math.h>
#include <stdint.h>

// ---------------- problem constants ----------------
#define T_TOK 8192
#define DMODEL 1024
#define NEXP 8
#define FDIM 4096
#define TWOF 8192
#define BM 128
#define MAXTILES (T_TOK / BM + NEXP) /* 72 */
#define PADMAX (MAXTILES * BM)       /* 9216 */
#define KC 32                        /* K-chunk in fp16 elements (64B/row) */
#define NTHREAD 512
#define CONVY 8                      /* extra grid.y rows in ffn1 doing Wout convert */

// smem stage: A(128x80) | B(256x80)
#define RS 80
#define OFF_B 10240
#define STAGEB 30720
#define NSTAGE 4
#define SMEMT (NSTAGE * STAGEB) /* 122880 */

// ---------------- device scratch ----------------
__device__ float g_gate_w[T_TOK];
__device__ int g_gate_idx[T_TOK];
__device__ float g_scores[NEXP];
__device__ int g_cnt[NEXP];
__device__ int g_fill[NEXP];
__device__ int g_poff[NEXP + 1];
__device__ int g_tile_expert[MAXTILES];
__device__ int g_perm[PADMAX];

__device__ __align__(16) __half g_xh[(size_t)PADMAX * DMODEL];
__device__ __align__(16) __half g_wfc[(size_t)NEXP * TWOF * DMODEL];
__device__ __align__(16) __half g_wout[(size_t)NEXP * DMODEL * FDIM];
__device__ __align__(16) __half g_act[(size_t)PADMAX * FDIM];

// ---------------- ptx helpers ----------------
__device__ __forceinline__ uint32_t smem_u32(const void* p) {
    uint32_t a;
    asm("{ .reg .u64 t; cvta.to.shared.u64 t, %1; cvt.u32.u64 %0, t; }" : "=r"(a) : "l"(p));
    return a;
}
__device__ __forceinline__ void cp16(uint32_t s, const void* g) {
    asm volatile("cp.async.cg.shared.global [%0], [%1], 16;" :: "r"(s), "l"(g));
}
#define CP_COMMIT asm volatile("cp.async.commit_group;" ::: "memory")
#define CP_WAIT2 asm volatile("cp.async.wait_group 2;" ::: "memory")

__device__ __forceinline__ void ldm4(uint32_t* r, uint32_t a) {
    asm volatile("ldmatrix.sync.aligned.m8n8.x4.shared.b16 {%0,%1,%2,%3}, [%4];"
                 : "=r"(r[0]), "=r"(r[1]), "=r"(r[2]), "=r"(r[3]) : "r"(a));
}
__device__ __forceinline__ void mma16816(float* c, const uint32_t* a, uint32_t b0, uint32_t b1) {
    asm volatile(
        "mma.sync.aligned.m16n8k16.row.col.f32.f16.f16.f32 "
        "{%0,%1,%2,%3}, {%4,%5,%6,%7}, {%8,%9}, {%0,%1,%2,%3};"
        : "+f"(c[0]), "+f"(c[1]), "+f"(c[2]), "+f"(c[3])
        : "r"(a[0]), "r"(a[1]), "r"(a[2]), "r"(a[3]), "r"(b0), "r"(b1));
}
__device__ __forceinline__ float gelu_exact(float v) {
    return 0.5f * v * (1.0f + erff(v * 0.70710678118654752f));
}

// ---------------- init: counters + tile map + perm fill + zero g_xh ----------------
__global__ void k_init() {
    int g = blockIdx.x * blockDim.x + threadIdx.x;
    if (g < NEXP) { g_scores[g] = 0.f; g_cnt[g] = 0; g_fill[g] = 0; }
    if (g < MAXTILES) g_tile_expert[g] = -1;
    for (int i = g; i < PADMAX; i += gridDim.x * blockDim.x) g_perm[i] = -1;
    const size_t n4 = (size_t)PADMAX * DMODEL / 8; // uint4 count
    uint4 z = make_uint4(0, 0, 0, 0);
    uint4* p = (uint4*)g_xh;
    for (size_t i = g; i < n4; i += (size_t)gridDim.x * blockDim.x) p[i] = z;
}

// ---------------- gating ----------------
__global__ void __launch_bounds__(256) k_gate(const float* __restrict__ x,
                                              const float* __restrict__ Wg,
                                              const float* __restrict__ bg) {
    __shared__ float s_sc[NEXP];
    __shared__ int s_ct[NEXP];
    int tid = threadIdx.x, lane = tid & 31, warp = tid >> 5;
    if (tid < NEXP) { s_sc[tid] = 0.f; s_ct[tid] = 0; }
    __syncthreads();
    int t = blockIdx.x * 8 + warp;
    float acc[NEXP];
#pragma unroll
    for (int e = 0; e < NEXP; e++) acc[e] = 0.f;
    const float* xr = x + (size_t)t * DMODEL;
    for (int d = lane; d < DMODEL; d += 32) {
        float xv = xr[d];
        const float* wr = Wg + d * NEXP;
#pragma unroll
        for (int e = 0; e < NEXP; e++) acc[e] += xv * wr[e];
    }
#pragma unroll
    for (int off = 16; off; off >>= 1)
#pragma unroll
        for (int e = 0; e < NEXP; e++) acc[e] += __shfl_xor_sync(0xffffffffu, acc[e], off);
    if (lane == 0) {
        float m = -1e30f;
        int idx = 0;
#pragma unroll
        for (int e = 0; e < NEXP; e++) {
            float l = acc[e] + bg[e];
            acc[e] = l;
            if (l > m) { m = l; idx = e; }
        }
        float s = 0.f;
#pragma unroll
        for (int e = 0; e < NEXP; e++) s += expf(acc[e] - m);
        float w = 1.0f / s;
        g_gate_w[t] = w;
        g_gate_idx[t] = idx;
        atomicAdd(&s_sc[idx], w);
        atomicAdd(&s_ct[idx], 1);
    }
    __syncthreads();
    if (tid < NEXP && s_ct[tid] > 0) {
        atomicAdd(&g_scores[tid], s_sc[tid]);
        atomicAdd(&g_cnt[tid], s_ct[tid]);
    }
}

// scan + utilization loss (tiny serial)
__global__ void k_scan(float* __restrict__ out, int loss_idx) {
    if (threadIdx.x == 0) {
        int off = 0;
        for (int e = 0; e < NEXP; e++) {
            g_poff[e] = off;
            int nt = (g_cnt[e] + BM - 1) / BM;
            int t0 = off / BM;
            for (int j = 0; j < nt; j++) g_tile_expert[t0 + j] = e;
            off += nt * BM;
        }
        g_poff[NEXP] = off;
        float L = 0.f;
        for (int e = 0; e < NEXP; e++) {
            float usage = g_scores[e] / ((float)g_cnt[e] + 1e-8f);
            float d = usage - 1.0f / (float)NEXP;
            L += d * d;
        }
        out[loss_idx] = L;
    }
}

// ---------------- fused scatter + permute/convert (block per token) ----------------
__global__ void __launch_bounds__(128) k_scatperm(const float* __restrict__ x) {
    __shared__ int s_pr;
    int t = blockIdx.x;
    if (threadIdx.x == 0) {
        int e = g_gate_idx[t];
        int p = atomicAdd(&g_fill[e], 1);
        int pr = g_poff[e] + p;
        g_perm[pr] = t;
        s_pr = pr;
    }
    __syncthreads();
    int pr = s_pr;
    const float4* xr = (const float4*)(x + (size_t)t * DMODEL);
    __half2* oh = (__half2*)(g_xh + (size_t)pr * DMODEL);
#pragma unroll
    for (int i = 0; i < 2; i++) {
        int idx = threadIdx.x + i * 128;
        float4 v = xr[idx];
        oh[idx * 2] = __floats2half2_rn(v.x, v.y);
        oh[idx * 2 + 1] = __floats2half2_rn(v.z, v.w);
    }
}

// ---------------- Wfc convert: 64(k) x 32(n) tiles, uint4 stores ----------------
__global__ void __launch_bounds__(256) k_convWfc(const float* __restrict__ Wfc) {
    __shared__ float tb[64][33];
    int e = blockIdx.z;
    int n0 = blockIdx.x * 32, k0 = blockIdx.y * 64;
    int tid = threadIdx.x;
#pragma unroll
    for (int i = 0; i < 8; i++) {
        int seg = tid + i * 256;
        int r = seg >> 5, cn = seg & 31;
        tb[r][cn] = Wfc[((size_t)e * DMODEL + k0 + r) * TWOF + n0 + cn];
    }
    __syncthreads();
    int n = tid >> 3, kq = tid & 7;
    __half h[8];
#pragma unroll
    for (int j = 0; j < 8; j++) h[j] = __float2half_rn(tb[kq * 8 + j][n]);
    *(uint4*)(g_wfc + ((size_t)e * TWOF + n0 + n) * DMODEL + k0 + kq * 8) = *(uint4*)h;
}

// ---------------- stage loaders (cp.async, 512 threads) ----------------
__device__ __forceinline__ void load1(uint32_t sbu, int buf, int k0, int row0, int f0,
                                      int e, int tid) {
    uint32_t sb = sbu + buf * STAGEB;
    {
        int r = tid >> 2, p = tid & 3;
        uint32_t off = r * RS + p * 16;
        size_t go = ((size_t)(row0 + r) * DMODEL + k0) * 2 + p * 16;
        cp16(sb + off, (const char*)g_xh + go);
    }
#pragma unroll
    for (int i = 0; i < 2; i++) {
        int seg = tid + i * NTHREAD;
        int n = seg >> 2, p = seg & 3;
        uint32_t off = n * RS + p * 16;
        int col = ((n & 1) ? FDIM : 0) + f0 + (n >> 1);
        size_t go = (((size_t)e * TWOF + col) * DMODEL + k0) * 2 + p * 16;
        cp16(sb + OFF_B + off, (const char*)g_wfc + go);
    }
}

__device__ __forceinline__ void load2(uint32_t sbu, int buf, int k0, int row0, int n0,
                                      int e, int tid) {
    uint32_t sb = sbu + buf * STAGEB;
    {
        int r = tid >> 2, p = tid & 3;
        uint32_t off = r * RS + p * 16;
        size_t go = ((size_t)(row0 + r) * FDIM + k0) * 2 + p * 16;
        cp16(sb + off, (const char*)g_act + go);
    }
#pragma unroll
    for (int i = 0; i < 2; i++) {
        int seg = tid + i * NTHREAD;
        int n = seg >> 2, p = seg & 3;
        uint32_t off = n * RS + p * 16;
        size_t go = (((size_t)e * DMODEL + n0 + n) * FDIM + k0) * 2 + p * 16;
        cp16(sb + OFF_B + off, (const char*)g_wout + go);
    }
}

// ---------------- chunk compute: fp16 mma, 16 warps, warp tile M64 x 32 B-rows ----------------
__device__ __forceinline__ void compute_chunk(uint32_t sbu, int buf, int lane, int wm,
                                              int wn, float c[4][4][4]) {
    uint32_t st = sbu + buf * STAGEB;
    uint32_t aRow = st + (uint32_t)(wm * 64 + (lane & 15)) * RS + (lane >> 4) * 16;
    uint32_t bRow = st + OFF_B +
                    (uint32_t)(wn * 32 + ((lane >> 4) & 1) * 8 + (lane & 7)) * RS +
                    ((lane >> 3) & 1) * 16;
#pragma unroll
    for (int ks = 0; ks < 2; ks++) {
        uint32_t ah[4][4];
#pragma unroll
        for (int mt = 0; mt < 4; mt++) ldm4(ah[mt], aRow + mt * 16 * RS + ks * 32);
#pragma unroll
        for (int q = 0; q < 2; q++) {
            uint32_t rh[4];
            ldm4(rh, bRow + q * 16 * RS + ks * 32);
#pragma unroll
            for (int mt = 0; mt < 4; mt++) {
                mma16816(c[mt][2 * q], ah[mt], rh[0], rh[1]);
                mma16816(c[mt][2 * q + 1], ah[mt], rh[2], rh[3]);
            }
        }
    }
}

// ---------------- GEMM1 + GLU (+ fused Wout convert in extra grid.y rows) ----------------
__global__ void __launch_bounds__(NTHREAD) k_ffn1(const float* __restrict__ bfc,
                                                  const float* __restrict__ Wout) {
    extern __shared__ char smem[];
    int tid = threadIdx.x;

    if (blockIdx.y >= MAXTILES) {
        // ---- Wout convert: [e][4096][1024] fp32 -> [e][1024][4096] fp16 ----
        float (*tb)[65] = (float(*)[65])smem;
        int cb = (blockIdx.y - MAXTILES) * gridDim.x + blockIdx.x; // 0..255
        const int NTILES = (FDIM / 64) * (DMODEL / 64) * NEXP;     // 8192
        for (int tile = cb; tile < NTILES; tile += gridDim.x * CONVY) {
            int e = tile >> 10;            // 1024 tiles per expert
            int rem = tile & 1023;
            int k0 = (rem >> 4) * 64, n0 = (rem & 15) * 64;
#pragma unroll
            for (int i = 0; i < 2; i++) {
                int f4 = tid + i * NTHREAD;
                int r = f4 >> 4, cn = (f4 & 15) * 4;
                float4 v = *(const float4*)(Wout + ((size_t)e * FDIM + k0 + r) * DMODEL + n0 + cn);
                tb[r][cn] = v.x; tb[r][cn + 1] = v.y; tb[r][cn + 2] = v.z; tb[r][cn + 3] = v.w;
            }
            __syncthreads();
            int n = tid >> 3, kq = tid & 7;
            __half h[8];
#pragma unroll
            for (int j = 0; j < 8; j++) h[j] = __float2half_rn(tb[kq * 8 + j][n]);
            *(uint4*)(g_wout + ((size_t)e * DMODEL + n0 + n) * FDIM + k0 + kq * 8) = *(uint4*)h;
            __syncthreads();
        }
        return;
    }

    int e = g_tile_expert[blockIdx.y];
    if (e < 0) return;
    uint32_t sbu = smem_u32(smem);
    int lane = tid & 31, warp = tid >> 5;
    int wm = warp & 1, wn = warp >> 1; // 2 x 8 warp grid
    int row0 = blockIdx.y * BM;
    int f0 = blockIdx.x * 128;
    const int NC = DMODEL / KC; // 32

    float c[4][4][4];
#pragma unroll
    for (int a = 0; a < 4; a++)
#pragma unroll
        for (int b = 0; b < 4; b++)
#pragma unroll
            for (int i = 0; i < 4; i++) c[a][b][i] = 0.f;

    load1(sbu, 0, 0, row0, f0, e, tid);
    CP_COMMIT;
    load1(sbu, 1, KC, row0, f0, e, tid);
    CP_COMMIT;
    load1(sbu, 2, 2 * KC, row0, f0, e, tid);
    CP_COMMIT;
    for (int ch = 0; ch < NC; ch++) {
        CP_WAIT2;
        __syncthreads();
        if (ch + 3 < NC) load1(sbu, (ch + 3) % NSTAGE, (ch + 3) * KC, row0, f0, e, tid);
        CP_COMMIT;
        compute_chunk(sbu, ch % NSTAGE, lane, wm, wn, c);
    }

    // GLU epilogue: accumulator pairs (even,odd) = (x1,x2) via interleaved B cols
    int jb = f0 + wn * 16 + (lane & 3);
    int rb = row0 + wm * 64 + (lane >> 2);
    const float* bb = bfc + (size_t)e * TWOF;
#pragma unroll
    for (int mt = 0; mt < 4; mt++)
#pragma unroll
        for (int nt = 0; nt < 4; nt++) {
            int j = jb + nt * 4;
            float b1 = bb[j], b2 = bb[FDIM + j];
#pragma unroll
            for (int pr2 = 0; pr2 < 2; pr2++) {
                int pr = rb + mt * 16 + pr2 * 8;
                float x1 = c[mt][nt][pr2 * 2] + b1;
                float x2 = c[mt][nt][pr2 * 2 + 1] + b2;
                g_act[(size_t)pr * FDIM + j] = __float2half_rn(x1 * gelu_exact(x2));
            }
        }
}

// ---------------- GEMM2 + scatter: CTA 128 x 256, 512 thr ----------------
__global__ void __launch_bounds__(NTHREAD) k_ffn2(const float* __restrict__ bout,
                                                  float* __restrict__ out) {
    int e = g_tile_expert[blockIdx.y];
    if (e < 0) return;
    extern __shared__ char smem[];
    uint32_t sbu = smem_u32(smem);
    int tid = threadIdx.x, lane = tid & 31, warp = tid >> 5;
    int wm = warp & 1, wn = warp >> 1;
    int row0 = blockIdx.y * BM;
    int n0 = blockIdx.x * 256;
    const int NC = FDIM / KC; // 128

    float c[4][4][4];
#pragma unroll
    for (int a = 0; a < 4; a++)
#pragma unroll
        for (int b = 0; b < 4; b++)
#pragma unroll
            for (int i = 0; i < 4; i++) c[a][b][i] = 0.f;

    load2(sbu, 0, 0, row0, n0, e, tid);
    CP_COMMIT;
    load2(sbu, 1, KC, row0, n0, e, tid);
    CP_COMMIT;
    load2(sbu, 2, 2 * KC, row0, n0, e, tid);
    CP_COMMIT;
    for (int ch = 0; ch < NC; ch++) {
        CP_WAIT2;
        __syncthreads();
        if (ch + 3 < NC) load2(sbu, (ch + 3) % NSTAGE, (ch + 3) * KC, row0, n0, e, tid);
        CP_COMMIT;
        compute_chunk(sbu, ch % NSTAGE, lane, wm, wn, c);
    }

    int nb = n0 + wn * 32 + (lane & 3) * 2;
    int rb = row0 + wm * 64 + (lane >> 2);
    const float* bo = bout + (size_t)e * DMODEL;
#pragma unroll
    for (int mt = 0; mt < 4; mt++)
#pragma unroll
        for (int pr2 = 0; pr2 < 2; pr2++) {
            int pr = rb + mt * 16 + pr2 * 8;
            int t = g_perm[pr];
            if (t < 0) continue;
            float w = g_gate_w[t];
            float* op = out + (size_t)t * DMODEL;
#pragma unroll
            for (int nt = 0; nt < 4; nt++) {
                int n = nb + nt * 8;
                float2 v;
                v.x = (c[mt][nt][pr2 * 2] + bo[n]) * w;
                v.y = (c[mt][nt][pr2 * 2 + 1] + bo[n + 1]) * w;
                *(float2*)(op + n) = v;
            }
        }
}

// ---------------- launch ----------------
extern "C" void kernel_launch(void* const* d_in, const int* in_sizes, int n_in,
                              void* d_out, int out_size) {
    const float* x = (const float*)d_in[0];
    const float* Wg = (const float*)d_in[1];
    const float* bg = (const float*)d_in[2];
    const float* Wfc = (const float*)d_in[3];
    const float* bfc = (const float*)d_in[4];
    const float* Wout = (const float*)d_in[5];
    const float* bout = (const float*)d_in[6];
    float* out = (float*)d_out;

    cudaFuncSetAttribute(k_ffn1, cudaFuncAttributeMaxDynamicSharedMemorySize, SMEMT);
    cudaFuncSetAttribute(k_ffn2, cudaFuncAttributeMaxDynamicSharedMemorySize, SMEMT);

    k_convWfc<<<dim3(TWOF / 32, DMODEL / 64, NEXP), 256>>>(Wfc);
    k_init<<<1024, 256>>>();
    k_gate<<<T_TOK / 8, 256>>>(x, Wg, bg);
    k_scan<<<1, 32>>>(out, out_size - 1);
    k_scatperm<<<T_TOK, 128>>>(x);
    k_ffn1<<<dim3(FDIM / 128, MAXTILES + CONVY), NTHREAD, SMEMT>>>(bfc, Wout);
    k_ffn2<<<dim3(DMODEL / 256, MAXTILES), NTHREAD, SMEMT>>>(bout, out);
}

// round 14
// speedup vs baseline: 1.1095x; 1.1095x over previous
#include <cuda_runtime.h>
#include <cuda_fp16.h>
#include <math.h>
#include <stdint.h>

// ---------------- problem constants ----------------
#define T_TOK 8192
#define DMODEL 1024
#define NEXP 8
#define FDIM 4096
#define TWOF 8192
#define BM 128
#define MAXTILES (T_TOK / BM + NEXP) /* 72 */
#define PADMAX (MAXTILES * BM)       /* 9216 */
#define KC 64                        /* K-chunk in fp16 elements (128B/row) */
#define NTHREAD 512

// smem stage: A(128x144B) | B(256x144B); 128B data + 16B pad per row
#define ROWB 144
#define OFF_B (128 * ROWB) /* 18432 */
#define STAGEB (384 * ROWB) /* 55296 */
#define NSTAGE 3
#define SMEMT (NSTAGE * STAGEB) /* 165888 */

// ---------------- device scratch ----------------
__device__ float g_gate_w[T_TOK];
__device__ int g_gate_idx[T_TOK];
__device__ float g_scores[NEXP];
__device__ int g_cnt[NEXP];
__device__ int g_fill[NEXP];
__device__ int g_poff[NEXP + 1];
__device__ int g_tile_expert[MAXTILES];
__device__ int g_perm[PADMAX];

__device__ __align__(16) __half g_xh[(size_t)PADMAX * DMODEL];
__device__ __align__(16) __half g_wfc[(size_t)NEXP * TWOF * DMODEL];
__device__ __align__(16) __half g_wout[(size_t)NEXP * DMODEL * FDIM];
__device__ __align__(16) __half g_act[(size_t)PADMAX * FDIM];

// ---------------- ptx helpers ----------------
__device__ __forceinline__ uint32_t smem_u32(const void* p) {
    uint32_t a;
    asm("{ .reg .u64 t; cvta.to.shared.u64 t, %1; cvt.u32.u64 %0, t; }" : "=r"(a) : "l"(p));
    return a;
}
__device__ __forceinline__ void cp16(uint32_t s, const void* g) {
    asm volatile("cp.async.cg.shared.global [%0], [%1], 16;" :: "r"(s), "l"(g));
}
#define CP_COMMIT asm volatile("cp.async.commit_group;" ::: "memory")
#define CP_WAIT1 asm volatile("cp.async.wait_group 1;" ::: "memory")

__device__ __forceinline__ void ldm4(uint32_t* r, uint32_t a) {
    asm volatile("ldmatrix.sync.aligned.m8n8.x4.shared.b16 {%0,%1,%2,%3}, [%4];"
                 : "=r"(r[0]), "=r"(r[1]), "=r"(r[2]), "=r"(r[3]) : "r"(a));
}
__device__ __forceinline__ void mma16816(float* c, const uint32_t* a, uint32_t b0, uint32_t b1) {
    asm volatile(
        "mma.sync.aligned.m16n8k16.row.col.f32.f16.f16.f32 "
        "{%0,%1,%2,%3}, {%4,%5,%6,%7}, {%8,%9}, {%0,%1,%2,%3};"
        : "+f"(c[0]), "+f"(c[1]), "+f"(c[2]), "+f"(c[3])
        : "r"(a[0]), "r"(a[1]), "r"(a[2]), "r"(a[3]), "r"(b0), "r"(b1));
}
__device__ __forceinline__ float gelu_exact(float v) {
    return 0.5f * v * (1.0f + erff(v * 0.70710678118654752f));
}

// ---------------- init: counters + tile map + perm fill ----------------
__global__ void k_init() {
    int g = blockIdx.x * blockDim.x + threadIdx.x;
    if (g < NEXP) { g_scores[g] = 0.f; g_cnt[g] = 0; g_fill[g] = 0; }
    if (g < MAXTILES) g_tile_expert[g] = -1;
    for (int i = g; i < PADMAX; i += gridDim.x * blockDim.x) g_perm[i] = -1;
}

// ---------------- gating ----------------
__global__ void __launch_bounds__(256) k_gate(const float* __restrict__ x,
                                              const float* __restrict__ Wg,
                                              const float* __restrict__ bg) {
    __shared__ float s_sc[NEXP];
    __shared__ int s_ct[NEXP];
    int tid = threadIdx.x, lane = tid & 31, warp = tid >> 5;
    if (tid < NEXP) { s_sc[tid] = 0.f; s_ct[tid] = 0; }
    __syncthreads();
    int t = blockIdx.x * 8 + warp;
    float acc[NEXP];
#pragma unroll
    for (int e = 0; e < NEXP; e++) acc[e] = 0.f;
    const float* xr = x + (size_t)t * DMODEL;
    for (int d = lane; d < DMODEL; d += 32) {
        float xv = xr[d];
        const float* wr = Wg + d * NEXP;
#pragma unroll
        for (int e = 0; e < NEXP; e++) acc[e] += xv * wr[e];
    }
#pragma unroll
    for (int off = 16; off; off >>= 1)
#pragma unroll
        for (int e = 0; e < NEXP; e++) acc[e] += __shfl_xor_sync(0xffffffffu, acc[e], off);
    if (lane == 0) {
        float m = -1e30f;
        int idx = 0;
#pragma unroll
        for (int e = 0; e < NEXP; e++) {
            float l = acc[e] + bg[e];
            acc[e] = l;
            if (l > m) { m = l; idx = e; }
        }
        float s = 0.f;
#pragma unroll
        for (int e = 0; e < NEXP; e++) s += expf(acc[e] - m);
        float w = 1.0f / s;
        g_gate_w[t] = w;
        g_gate_idx[t] = idx;
        atomicAdd(&s_sc[idx], w);
        atomicAdd(&s_ct[idx], 1);
    }
    __syncthreads();
    if (tid < NEXP && s_ct[tid] > 0) {
        atomicAdd(&g_scores[tid], s_sc[tid]);
        atomicAdd(&g_cnt[tid], s_ct[tid]);
    }
}

// scan + utilization loss (tiny serial)
__global__ void k_scan(float* __restrict__ out, int loss_idx) {
    if (threadIdx.x == 0) {
        int off = 0;
        for (int e = 0; e < NEXP; e++) {
            g_poff[e] = off;
            int nt = (g_cnt[e] + BM - 1) / BM;
            int t0 = off / BM;
            for (int j = 0; j < nt; j++) g_tile_expert[t0 + j] = e;
            off += nt * BM;
        }
        g_poff[NEXP] = off;
        float L = 0.f;
        for (int e = 0; e < NEXP; e++) {
            float usage = g_scores[e] / ((float)g_cnt[e] + 1e-8f);
            float d = usage - 1.0f / (float)NEXP;
            L += d * d;
        }
        out[loss_idx] = L;
    }
}

// ---------------- fused scatter + permute/convert (block per token) ----------------
__global__ void __launch_bounds__(128) k_scatperm(const float* __restrict__ x) {
    __shared__ int s_pr;
    int t = blockIdx.x;
    if (threadIdx.x == 0) {
        int e = g_gate_idx[t];
        int p = atomicAdd(&g_fill[e], 1);
        int pr = g_poff[e] + p;
        g_perm[pr] = t;
        s_pr = pr;
    }
    __syncthreads();
    int pr = s_pr;
    const float4* xr = (const float4*)(x + (size_t)t * DMODEL);
    __half2* oh = (__half2*)(g_xh + (size_t)pr * DMODEL);
#pragma unroll
    for (int i = 0; i < 2; i++) {
        int idx = threadIdx.x + i * 128;
        float4 v = xr[idx];
        oh[idx * 2] = __floats2half2_rn(v.x, v.y);
        oh[idx * 2 + 1] = __floats2half2_rn(v.z, v.w);
    }
}

// ---------------- weight converts: 64(k) x 32(n) tiles, uint4 stores ----------------
// src [e][K][N] fp32 -> dst [e][N][K] fp16
template <int KD, int ND>
__device__ __forceinline__ void conv_tile(const float* __restrict__ src,
                                          __half* __restrict__ dst) {
    __shared__ float tb[64][33];
    int e = blockIdx.z;
    int n0 = blockIdx.x * 32, k0 = blockIdx.y * 64;
    int tid = threadIdx.x;
#pragma unroll
    for (int i = 0; i < 8; i++) {
        int seg = tid + i * 256;
        int r = seg >> 5, cn = seg & 31;
        tb[r][cn] = src[((size_t)e * KD + k0 + r) * ND + n0 + cn];
    }
    __syncthreads();
    int n = tid >> 3, kq = tid & 7;
    __half h[8];
#pragma unroll
    for (int j = 0; j < 8; j++) h[j] = __float2half_rn(tb[kq * 8 + j][n]);
    *(uint4*)(dst + ((size_t)e * ND + n0 + n) * KD + k0 + kq * 8) = *(uint4*)h;
}

__global__ void __launch_bounds__(256) k_convWfc(const float* __restrict__ Wfc) {
    conv_tile<DMODEL, TWOF>(Wfc, g_wfc);
}
__global__ void __launch_bounds__(256) k_convWout(const float* __restrict__ Wout) {
    conv_tile<FDIM, DMODEL>(Wout, g_wout);
}

// ---------------- stage loaders (cp.async, 512 threads, 128B rows) ----------------
// A: 128 rows x 128B = 1024 segs (2/thread). B: 256 rows x 128B = 2048 segs (4/thread).
__device__ __forceinline__ void load1(uint32_t sbu, int buf, int k0, int row0, int f0,
                                      int e, int tid) {
    uint32_t sb = sbu + buf * STAGEB;
#pragma unroll
    for (int i = 0; i < 2; i++) {
        int seg = tid + i * NTHREAD;
        int r = seg >> 3, p = seg & 7;
        uint32_t off = r * ROWB + p * 16;
        size_t go = ((size_t)(row0 + r) * DMODEL + k0) * 2 + p * 16;
        cp16(sb + off, (const char*)g_xh + go);
    }
#pragma unroll
    for (int i = 0; i < 4; i++) {
        int seg = tid + i * NTHREAD;
        int n = seg >> 3, p = seg & 7;
        uint32_t off = n * ROWB + p * 16;
        int col = ((n & 1) ? FDIM : 0) + f0 + (n >> 1);
        size_t go = (((size_t)e * TWOF + col) * DMODEL + k0) * 2 + p * 16;
        cp16(sb + OFF_B + off, (const char*)g_wfc + go);
    }
}

__device__ __forceinline__ void load2(uint32_t sbu, int buf, int k0, int row0, int n0,
                                      int e, int tid) {
    uint32_t sb = sbu + buf * STAGEB;
#pragma unroll
    for (int i = 0; i < 2; i++) {
        int seg = tid + i * NTHREAD;
        int r = seg >> 3, p = seg & 7;
        uint32_t off = r * ROWB + p * 16;
        size_t go = ((size_t)(row0 + r) * FDIM + k0) * 2 + p * 16;
        cp16(sb + off, (const char*)g_act + go);
    }
#pragma unroll
    for (int i = 0; i < 4; i++) {
        int seg = tid + i * NTHREAD;
        int n = seg >> 3, p = seg & 7;
        uint32_t off = n * ROWB + p * 16;
        size_t go = (((size_t)e * DMODEL + n0 + n) * FDIM + k0) * 2 + p * 16;
        cp16(sb + OFF_B + off, (const char*)g_wout + go);
    }
}

// ---------------- chunk compute: fp16 mma, 16 warps, warp tile M64 x 32 B-rows, K=64 ----------------
__device__ __forceinline__ void compute_chunk(uint32_t sbu, int buf, int lane, int wm,
                                              int wn, float c[4][4][4]) {
    uint32_t st = sbu + buf * STAGEB;
    uint32_t aRow = st + (uint32_t)(wm * 64 + (lane & 15)) * ROWB + (lane >> 4) * 16;
    uint32_t bRow = st + OFF_B +
                    (uint32_t)(wn * 32 + ((lane >> 4) & 1) * 8 + (lane & 7)) * ROWB +
                    ((lane >> 3) & 1) * 16;
#pragma unroll
    for (int ks = 0; ks < 4; ks++) {
        uint32_t ah[4][4];
#pragma unroll
        for (int mt = 0; mt < 4; mt++) ldm4(ah[mt], aRow + mt * 16 * ROWB + ks * 32);
#pragma unroll
        for (int q = 0; q < 2; q++) {
            uint32_t rh[4];
            ldm4(rh, bRow + q * 16 * ROWB + ks * 32);
#pragma unroll
            for (int mt = 0; mt < 4; mt++) {
                mma16816(c[mt][2 * q], ah[mt], rh[0], rh[1]);
                mma16816(c[mt][2 * q + 1], ah[mt], rh[2], rh[3]);
            }
        }
    }
}

// ---------------- GEMM1 + GLU: CTA 128 x 128 output cols, 512 thr ----------------
__global__ void __launch_bounds__(NTHREAD) k_ffn1(const float* __restrict__ bfc) {
    int e = g_tile_expert[blockIdx.y];
    if (e < 0) return;
    extern __shared__ char smem[];
    uint32_t sbu = smem_u32(smem);
    int tid = threadIdx.x, lane = tid & 31, warp = tid >> 5;
    int wm = warp & 1, wn = warp >> 1; // 2 x 8 warp grid
    int row0 = blockIdx.y * BM;
    int f0 = blockIdx.x * 128;
    const int NC = DMODEL / KC; // 16

    float c[4][4][4];
#pragma unroll
    for (int a = 0; a < 4; a++)
#pragma unroll
        for (int b = 0; b < 4; b++)
#pragma unroll
            for (int i = 0; i < 4; i++) c[a][b][i] = 0.f;

    load1(sbu, 0, 0, row0, f0, e, tid);
    CP_COMMIT;
    load1(sbu, 1, KC, row0, f0, e, tid);
    CP_COMMIT;
    for (int ch = 0; ch < NC; ch++) {
        CP_WAIT1;
        __syncthreads();
        if (ch + 2 < NC) load1(sbu, (ch + 2) % NSTAGE, (ch + 2) * KC, row0, f0, e, tid);
        CP_COMMIT;
        compute_chunk(sbu, ch % NSTAGE, lane, wm, wn, c);
    }

    // GLU epilogue: accumulator pairs (even,odd) = (x1,x2) via interleaved B cols
    int jb = f0 + wn * 16 + (lane & 3);
    int rb = row0 + wm * 64 + (lane >> 2);
    const float* bb = bfc + (size_t)e * TWOF;
#pragma unroll
    for (int mt = 0; mt < 4; mt++)
#pragma unroll
        for (int nt = 0; nt < 4; nt++) {
            int j = jb + nt * 4;
            float b1 = bb[j], b2 = bb[FDIM + j];
#pragma unroll
            for (int pr2 = 0; pr2 < 2; pr2++) {
                int pr = rb + mt * 16 + pr2 * 8;
                float x1 = c[mt][nt][pr2 * 2] + b1;
                float x2 = c[mt][nt][pr2 * 2 + 1] + b2;
                g_act[(size_t)pr * FDIM + j] = __float2half_rn(x1 * gelu_exact(x2));
            }
        }
}

// ---------------- GEMM2 + scatter: CTA 128 x 256, 512 thr ----------------
__global__ void __launch_bounds__(NTHREAD) k_ffn2(const float* __restrict__ bout,
                                                  float* __restrict__ out) {
    int e = g_tile_expert[blockIdx.y];
    if (e < 0) return;
    extern __shared__ char smem[];
    uint32_t sbu = smem_u32(smem);
    int tid = threadIdx.x, lane = tid & 31, warp = tid >> 5;
    int wm = warp & 1, wn = warp >> 1;
    int row0 = blockIdx.y * BM;
    int n0 = blockIdx.x * 256;
    const int NC = FDIM / KC; // 64

    float c[4][4][4];
#pragma unroll
    for (int a = 0; a < 4; a++)
#pragma unroll
        for (int b = 0; b < 4; b++)
#pragma unroll
            for (int i = 0; i < 4; i++) c[a][b][i] = 0.f;

    load2(sbu, 0, 0, row0, n0, e, tid);
    CP_COMMIT;
    load2(sbu, 1, KC, row0, n0, e, tid);
    CP_COMMIT;
    for (int ch = 0; ch < NC; ch++) {
        CP_WAIT1;
        __syncthreads();
        if (ch + 2 < NC) load2(sbu, (ch + 2) % NSTAGE, (ch + 2) * KC, row0, n0, e, tid);
        CP_COMMIT;
        compute_chunk(sbu, ch % NSTAGE, lane, wm, wn, c);
    }

    int nb = n0 + wn * 32 + (lane & 3) * 2;
    int rb = row0 + wm * 64 + (lane >> 2);
    const float* bo = bout + (size_t)e * DMODEL;
#pragma unroll
    for (int mt = 0; mt < 4; mt++)
#pragma unroll
        for (int pr2 = 0; pr2 < 2; pr2++) {
            int pr = rb + mt * 16 + pr2 * 8;
            int t = g_perm[pr];
            if (t < 0) continue;
            float w = g_gate_w[t];
            float* op = out + (size_t)t * DMODEL;
#pragma unroll
            for (int nt = 0; nt < 4; nt++) {
                int n = nb + nt * 8;
                float2 v;
                v.x = (c[mt][nt][pr2 * 2] + bo[n]) * w;
                v.y = (c[mt][nt][pr2 * 2 + 1] + bo[n + 1]) * w;
                *(float2*)(op + n) = v;
            }
        }
}

// ---------------- launch ----------------
extern "C" void kernel_launch(void* const* d_in, const int* in_sizes, int n_in,
                              void* d_out, int out_size) {
    const float* x = (const float*)d_in[0];
    const float* Wg = (const float*)d_in[1];
    const float* bg = (const float*)d_in[2];
    const float* Wfc = (const float*)d_in[3];
    const float* bfc = (const float*)d_in[4];
    const float* Wout = (const float*)d_in[5];
    const float* bout = (const float*)d_in[6];
    float* out = (float*)d_out;

    cudaFuncSetAttribute(k_ffn1, cudaFuncAttributeMaxDynamicSharedMemorySize, SMEMT);
    cudaFuncSetAttribute(k_ffn2, cudaFuncAttributeMaxDynamicSharedMemorySize, SMEMT);

    k_convWfc<<<dim3(TWOF / 32, DMODEL / 64, NEXP), 256>>>(Wfc);
    k_init<<<64, 256>>>();
    k_gate<<<T_TOK / 8, 256>>>(x, Wg, bg);
    k_scan<<<1, 32>>>(out, out_size - 1);
    k_scatperm<<<T_TOK, 128>>>(x);
    k_ffn1<<<dim3(FDIM / 128, MAXTILES), NTHREAD, SMEMT>>>(bfc);
    k_convWout<<<dim3(DMODEL / 32, FDIM / 64, NEXP), 256>>>(Wout);
    k_ffn2<<<dim3(DMODEL / 256, MAXTILES), NTHREAD, SMEMT>>>(bout, out);
}

// round 16
// speedup vs baseline: 1.1189x; 1.0085x over previous
#include <cuda_runtime.h>
#include <cuda_fp16.h>
#include <math.h>
#include <stdint.h>

// ---------------- problem constants ----------------
#define T_TOK 8192
#define DMODEL 1024
#define NEXP 8
#define FDIM 4096
#define TWOF 8192
#define BM 128
#define MAXTILES (T_TOK / BM + NEXP) /* 72 */
#define PADMAX (MAXTILES * BM)       /* 9216 */
#define KC 64                        /* K-chunk in fp16 elements (128B/row) */
#define NTHREAD 512

// combo grid split
#define GATE_BLOCKS (T_TOK / 8)                      /* 1024 */
#define WFC_BLOCKS ((TWOF / 32) * (DMODEL / 64) * NEXP)  /* 32768 */
#define WOUT_BLOCKS ((DMODEL / 32) * (FDIM / 64) * NEXP) /* 16384 */
#define COMBO_BLOCKS (GATE_BLOCKS + WFC_BLOCKS + WOUT_BLOCKS)

// smem stage: A(128x144B) | B(256x144B); 128B data + 16B pad per row
#define ROWB 144
#define OFF_B (128 * ROWB) /* 18432 */
#define STAGEB (384 * ROWB) /* 55296 */
#define NSTAGE 3
#define SMEMT (NSTAGE * STAGEB) /* 165888 */

// ---------------- device scratch ----------------
__device__ float g_gate_w[T_TOK];
__device__ int g_gate_idx[T_TOK];
__device__ float g_scores[NEXP];
__device__ int g_cnt[NEXP];
__device__ int g_fill[NEXP];
__device__ int g_tile_expert[MAXTILES];
__device__ int g_perm[PADMAX];

__device__ __align__(16) __half g_xh[(size_t)PADMAX * DMODEL];
__device__ __align__(16) __half g_wfc[(size_t)NEXP * TWOF * DMODEL];
__device__ __align__(16) __half g_wout[(size_t)NEXP * DMODEL * FDIM];
__device__ __align__(16) __half g_act[(size_t)PADMAX * FDIM];

// ---------------- ptx helpers ----------------
__device__ __forceinline__ uint32_t smem_u32(const void* p) {
    uint32_t a;
    asm("{ .reg .u64 t; cvta.to.shared.u64 t, %1; cvt.u32.u64 %0, t; }" : "=r"(a) : "l"(p));
    return a;
}
__device__ __forceinline__ void cp16(uint32_t s, const void* g) {
    asm volatile("cp.async.cg.shared.global [%0], [%1], 16;" :: "r"(s), "l"(g));
}
#define CP_COMMIT asm volatile("cp.async.commit_group;" ::: "memory")
#define CP_WAIT1 asm volatile("cp.async.wait_group 1;" ::: "memory")

__device__ __forceinline__ void ldm4(uint32_t* r, uint32_t a) {
    asm volatile("ldmatrix.sync.aligned.m8n8.x4.shared.b16 {%0,%1,%2,%3}, [%4];"
                 : "=r"(r[0]), "=r"(r[1]), "=r"(r[2]), "=r"(r[3]) : "r"(a));
}
__device__ __forceinline__ void mma16816(float* c, const uint32_t* a, uint32_t b0, uint32_t b1) {
    asm volatile(
        "mma.sync.aligned.m16n8k16.row.col.f32.f16.f16.f32 "
        "{%0,%1,%2,%3}, {%4,%5,%6,%7}, {%8,%9}, {%0,%1,%2,%3};"
        : "+f"(c[0]), "+f"(c[1]), "+f"(c[2]), "+f"(c[3])
        : "r"(a[0]), "r"(a[1]), "r"(a[2]), "r"(a[3]), "r"(b0), "r"(b1));
}
__device__ __forceinline__ float gelu_exact(float v) {
    return 0.5f * v * (1.0f + erff(v * 0.70710678118654752f));
}

// ---------------- init: counters + tile map + perm fill ----------------
__global__ void k_init() {
    int g = blockIdx.x * blockDim.x + threadIdx.x;
    if (g < NEXP) { g_scores[g] = 0.f; g_cnt[g] = 0; g_fill[g] = 0; }
    if (g < MAXTILES) g_tile_expert[g] = -1;
    for (int i = g; i < PADMAX; i += gridDim.x * blockDim.x) g_perm[i] = -1;
}

// ---------------- combo: gate | convWfc | convWout (independent work) ----------------
__device__ __forceinline__ void gate_body(const float* __restrict__ x,
                                          const float* __restrict__ Wg,
                                          const float* __restrict__ bg,
                                          char* sm, int bid) {
    float* s_sc = (float*)sm;
    int* s_ct = (int*)(sm + NEXP * 4);
    int tid = threadIdx.x, lane = tid & 31, warp = tid >> 5;
    if (tid < NEXP) { s_sc[tid] = 0.f; s_ct[tid] = 0; }
    __syncthreads();
    int t = bid * 8 + warp;
    float acc[NEXP];
#pragma unroll
    for (int e = 0; e < NEXP; e++) acc[e] = 0.f;
    const float* xr = x + (size_t)t * DMODEL;
    for (int d = lane; d < DMODEL; d += 32) {
        float xv = xr[d];
        const float* wr = Wg + d * NEXP;
#pragma unroll
        for (int e = 0; e < NEXP; e++) acc[e] += xv * wr[e];
    }
#pragma unroll
    for (int off = 16; off; off >>= 1)
#pragma unroll
        for (int e = 0; e < NEXP; e++) acc[e] += __shfl_xor_sync(0xffffffffu, acc[e], off);
    if (lane == 0) {
        float m = -1e30f;
        int idx = 0;
#pragma unroll
        for (int e = 0; e < NEXP; e++) {
            float l = acc[e] + bg[e];
            acc[e] = l;
            if (l > m) { m = l; idx = e; }
        }
        float s = 0.f;
#pragma unroll
        for (int e = 0; e < NEXP; e++) s += expf(acc[e] - m);
        float w = 1.0f / s;
        g_gate_w[t] = w;
        g_gate_idx[t] = idx;
        atomicAdd(&s_sc[idx], w);
        atomicAdd(&s_ct[idx], 1);
    }
    __syncthreads();
    if (tid < NEXP && s_ct[tid] > 0) {
        atomicAdd(&g_scores[tid], s_sc[tid]);
        atomicAdd(&g_cnt[tid], s_ct[tid]);
    }
}

// src [e][K][N] fp32 -> dst [e][N][K] fp16; 64(k) x 32(n) tile
template <int KD, int ND>
__device__ __forceinline__ void conv_body(const float* __restrict__ src,
                                          __half* __restrict__ dst, char* sm,
                                          int e, int n0, int k0) {
    float (*tb)[33] = (float(*)[33])sm;
    int tid = threadIdx.x;
#pragma unroll
    for (int i = 0; i < 8; i++) {
        int seg = tid + i * 256;
        int r = seg >> 5, cn = seg & 31;
        tb[r][cn] = src[((size_t)e * KD + k0 + r) * ND + n0 + cn];
    }
    __syncthreads();
    int n = tid >> 3, kq = tid & 7;
    __half h[8];
#pragma unroll
    for (int j = 0; j < 8; j++) h[j] = __float2half_rn(tb[kq * 8 + j][n]);
    *(uint4*)(dst + ((size_t)e * ND + n0 + n) * KD + k0 + kq * 8) = *(uint4*)h;
}

__global__ void __launch_bounds__(256) k_combo(const float* __restrict__ x,
                                               const float* __restrict__ Wg,
                                               const float* __restrict__ bg,
                                               const float* __restrict__ Wfc,
                                               const float* __restrict__ Wout) {
    __shared__ __align__(16) char sm[64 * 33 * 4];
    int bid = blockIdx.x;
    if (bid < GATE_BLOCKS) {
        gate_body(x, Wg, bg, sm, bid);
    } else if (bid < GATE_BLOCKS + WFC_BLOCKS) {
        int b = bid - GATE_BLOCKS;
        int n0 = (b & 255) * 32, k0 = ((b >> 8) & 15) * 64, e = b >> 12;
        conv_body<DMODEL, TWOF>(Wfc, g_wfc, sm, e, n0, k0);
    } else {
        int b = bid - GATE_BLOCKS - WFC_BLOCKS;
        int n0 = (b & 31) * 32, k0 = ((b >> 5) & 63) * 64, e = b >> 11;
        conv_body<FDIM, DMODEL>(Wout, g_wout, sm, e, n0, k0);
    }
}

// ---------------- scatter + permute/convert; block 0 also writes tile map + loss ----------------
__global__ void __launch_bounds__(128) k_scatperm(const float* __restrict__ x,
                                                  float* __restrict__ out, int loss_idx) {
    __shared__ int s_pr;
    int t = blockIdx.x;
    if (threadIdx.x == 0) {
        int e = g_gate_idx[t];
        int off = 0, myoff = 0;
#pragma unroll
        for (int i = 0; i < NEXP; i++) {
            if (i == e) myoff = off;
            off += ((g_cnt[i] + BM - 1) / BM) * BM;
        }
        int p = atomicAdd(&g_fill[e], 1);
        int pr = myoff + p;
        g_perm[pr] = t;
        s_pr = pr;
        if (t == 0) {
            // tile->expert map + utilization loss (serial, tiny)
            int o2 = 0;
            float L = 0.f;
            for (int e2 = 0; e2 < NEXP; e2++) {
                int nt = (g_cnt[e2] + BM - 1) / BM;
                int t0 = o2 / BM;
                for (int j = 0; j < nt; j++) g_tile_expert[t0 + j] = e2;
                o2 += nt * BM;
                float usage = g_scores[e2] / ((float)g_cnt[e2] + 1e-8f);
                float d = usage - 1.0f / (float)NEXP;
                L += d * d;
            }
            out[loss_idx] = L;
        }
    }
    __syncthreads();
    int pr = s_pr;
    const float4* xr = (const float4*)(x + (size_t)t * DMODEL);
    __half2* oh = (__half2*)(g_xh + (size_t)pr * DMODEL);
#pragma unroll
    for (int i = 0; i < 2; i++) {
        int idx = threadIdx.x + i * 128;
        float4 v = xr[idx];
        oh[idx * 2] = __floats2half2_rn(v.x, v.y);
        oh[idx * 2 + 1] = __floats2half2_rn(v.z, v.w);
    }
}

// ---------------- stage loaders (cp.async, 512 threads, 128B rows) ----------------
__device__ __forceinline__ void load1(uint32_t sbu, int buf, int k0, int row0, int f0,
                                      int e, int tid) {
    uint32_t sb = sbu + buf * STAGEB;
#pragma unroll
    for (int i = 0; i < 2; i++) {
        int seg = tid + i * NTHREAD;
        int r = seg >> 3, p = seg & 7;
        uint32_t off = r * ROWB + p * 16;
        size_t go = ((size_t)(row0 + r) * DMODEL + k0) * 2 + p * 16;
        cp16(sb + off, (const char*)g_xh + go);
    }
#pragma unroll
    for (int i = 0; i < 4; i++) {
        int seg = tid + i * NTHREAD;
        int n = seg >> 3, p = seg & 7;
        uint32_t off = n * ROWB + p * 16;
        int col = ((n & 1) ? FDIM : 0) + f0 + (n >> 1);
        size_t go = (((size_t)e * TWOF + col) * DMODEL + k0) * 2 + p * 16;
        cp16(sb + OFF_B + off, (const char*)g_wfc + go);
    }
}

__device__ __forceinline__ void load2(uint32_t sbu, int buf, int k0, int row0, int n0,
                                      int e, int tid) {
    uint32_t sb = sbu + buf * STAGEB;
#pragma unroll
    for (int i = 0; i < 2; i++) {
        int seg = tid + i * NTHREAD;
        int r = seg >> 3, p = seg & 7;
        uint32_t off = r * ROWB + p * 16;
        size_t go = ((size_t)(row0 + r) * FDIM + k0) * 2 + p * 16;
        cp16(sb + off, (const char*)g_act + go);
    }
#pragma unroll
    for (int i = 0; i < 4; i++) {
        int seg = tid + i * NTHREAD;
        int n = seg >> 3, p = seg & 7;
        uint32_t off = n * ROWB + p * 16;
        size_t go = (((size_t)e * DMODEL + n0 + n) * FDIM + k0) * 2 + p * 16;
        cp16(sb + OFF_B + off, (const char*)g_wout + go);
    }
}

// ---------------- chunk compute: fp16 mma, 16 warps, warp tile M64 x 32 B-rows, K=64 ----------------
__device__ __forceinline__ void compute_chunk(uint32_t sbu, int buf, int lane, int wm,
                                              int wn, float c[4][4][4]) {
    uint32_t st = sbu + buf * STAGEB;
    uint32_t aRow = st + (uint32_t)(wm * 64 + (lane & 15)) * ROWB + (lane >> 4) * 16;
    uint32_t bRow = st + OFF_B +
                    (uint32_t)(wn * 32 + ((lane >> 4) & 1) * 8 + (lane & 7)) * ROWB +
                    ((lane >> 3) & 1) * 16;
#pragma unroll
    for (int ks = 0; ks < 4; ks++) {
        uint32_t ah[4][4];
#pragma unroll
        for (int mt = 0; mt < 4; mt++) ldm4(ah[mt], aRow + mt * 16 * ROWB + ks * 32);
#pragma unroll
        for (int q = 0; q < 2; q++) {
            uint32_t rh[4];
            ldm4(rh, bRow + q * 16 * ROWB + ks * 32);
#pragma unroll
            for (int mt = 0; mt < 4; mt++) {
                mma16816(c[mt][2 * q], ah[mt], rh[0], rh[1]);
                mma16816(c[mt][2 * q + 1], ah[mt], rh[2], rh[3]);
            }
        }
    }
}

// ---------------- GEMM1 + GLU: CTA 128 x 128 output cols, 512 thr ----------------
__global__ void __launch_bounds__(NTHREAD) k_ffn1(const float* __restrict__ bfc) {
    int e = g_tile_expert[blockIdx.y];
    if (e < 0) return;
    extern __shared__ char smem[];
    uint32_t sbu = smem_u32(smem);
    int tid = threadIdx.x, lane = tid & 31, warp = tid >> 5;
    int wm = warp & 1, wn = warp >> 1; // 2 x 8 warp grid
    int row0 = blockIdx.y * BM;
    int f0 = blockIdx.x * 128;
    const int NC = DMODEL / KC; // 16

    float c[4][4][4];
#pragma unroll
    for (int a = 0; a < 4; a++)
#pragma unroll
        for (int b = 0; b < 4; b++)
#pragma unroll
            for (int i = 0; i < 4; i++) c[a][b][i] = 0.f;

    load1(sbu, 0, 0, row0, f0, e, tid);
    CP_COMMIT;
    load1(sbu, 1, KC, row0, f0, e, tid);
    CP_COMMIT;
    for (int ch = 0; ch < NC; ch++) {
        CP_WAIT1;
        __syncthreads();
        if (ch + 2 < NC) load1(sbu, (ch + 2) % NSTAGE, (ch + 2) * KC, row0, f0, e, tid);
        CP_COMMIT;
        compute_chunk(sbu, ch % NSTAGE, lane, wm, wn, c);
    }

    // GLU epilogue: accumulator pairs (even,odd) = (x1,x2) via interleaved B cols
    int jb = f0 + wn * 16 + (lane & 3);
    int rb = row0 + wm * 64 + (lane >> 2);
    const float* bb = bfc + (size_t)e * TWOF;
#pragma unroll
    for (int mt = 0; mt < 4; mt++)
#pragma unroll
        for (int nt = 0; nt < 4; nt++) {
            int j = jb + nt * 4;
            float b1 = bb[j], b2 = bb[FDIM + j];
#pragma unroll
            for (int pr2 = 0; pr2 < 2; pr2++) {
                int pr = rb + mt * 16 + pr2 * 8;
                float x1 = c[mt][nt][pr2 * 2] + b1;
                float x2 = c[mt][nt][pr2 * 2 + 1] + b2;
                g_act[(size_t)pr * FDIM + j] = __float2half_rn(x1 * gelu_exact(x2));
            }
        }
}

// ---------------- GEMM2 + scatter: CTA 128 x 256, 512 thr ----------------
__global__ void __launch_bounds__(NTHREAD) k_ffn2(const float* __restrict__ bout,
                                                  float* __restrict__ out) {
    int e = g_tile_expert[blockIdx.y];
    if (e < 0) return;
    extern __shared__ char smem[];
    uint32_t sbu = smem_u32(smem);
    int tid = threadIdx.x, lane = tid & 31, warp = tid >> 5;
    int wm = warp & 1, wn = warp >> 1;
    int row0 = blockIdx.y * BM;
    int n0 = blockIdx.x * 256;
    const int NC = FDIM / KC; // 64

    float c[4][4][4];
#pragma unroll
    for (int a = 0; a < 4; a++)
#pragma unroll
        for (int b = 0; b < 4; b++)
#pragma unroll
            for (int i = 0; i < 4; i++) c[a][b][i] = 0.f;

    load2(sbu, 0, 0, row0, n0, e, tid);
    CP_COMMIT;
    load2(sbu, 1, KC, row0, n0, e, tid);
    CP_COMMIT;
    for (int ch = 0; ch < NC; ch++) {
        CP_WAIT1;
        __syncthreads();
        if (ch + 2 < NC) load2(sbu, (ch + 2) % NSTAGE, (ch + 2) * KC, row0, n0, e, tid);
        CP_COMMIT;
        compute_chunk(sbu, ch % NSTAGE, lane, wm, wn, c);
    }

    int nb = n0 + wn * 32 + (lane & 3) * 2;
    int rb = row0 + wm * 64 + (lane >> 2);
    const float* bo = bout + (size_t)e * DMODEL;
#pragma unroll
    for (int mt = 0; mt < 4; mt++)
#pragma unroll
        for (int pr2 = 0; pr2 < 2; pr2++) {
            int pr = rb + mt * 16 + pr2 * 8;
            int t = g_perm[pr];
            if (t < 0) continue;
            float w = g_gate_w[t];
            float* op = out + (size_t)t * DMODEL;
#pragma unroll
            for (int nt = 0; nt < 4; nt++) {
                int n = nb + nt * 8;
                float2 v;
                v.x = (c[mt][nt][pr2 * 2] + bo[n]) * w;
                v.y = (c[mt][nt][pr2 * 2 + 1] + bo[n + 1]) * w;
                *(float2*)(op + n) = v;
            }
        }
}

// ---------------- launch ----------------
extern "C" void kernel_launch(void* const* d_in, const int* in_sizes, int n_in,
                              void* d_out, int out_size) {
    const float* x = (const float*)d_in[0];
    const float* Wg = (const float*)d_in[1];
    const float* bg = (const float*)d_in[2];
    const float* Wfc = (const float*)d_in[3];
    const float* bfc = (const float*)d_in[4];
    const float* Wout = (const float*)d_in[5];
    const float* bout = (const float*)d_in[6];
    float* out = (float*)d_out;

    cudaFuncSetAttribute(k_ffn1, cudaFuncAttributeMaxDynamicSharedMemorySize, SMEMT);
    cudaFuncSetAttribute(k_ffn2, cudaFuncAttributeMaxDynamicSharedMemorySize, SMEMT);

    k_init<<<64, 256>>>();
    k_combo<<<COMBO_BLOCKS, 256>>>(x, Wg, bg, Wfc, Wout);
    k_scatperm<<<T_TOK, 128>>>(x, out, out_size - 1);
    k_ffn1<<<dim3(FDIM / 128, MAXTILES), NTHREAD, SMEMT>>>(bfc);
    k_ffn2<<<dim3(DMODEL / 256, MAXTILES), NTHREAD, SMEMT>>>(bout, out);
}